// round 3
// baseline (speedup 1.0000x reference)
#include <cuda_runtime.h>
#include <cuda_bf16.h>
#include <math.h>

// Problem constants (fixed by reference setup_inputs):
//   n = 100000 nodes, seq_len = 4, hidden = 128, n_edges = 1.6M
#define MAX_N      100000
#define MAX_EDGES  1600000
#define HIDDEN     128
#define SEQ_STRIDE (4 * 128)   // floats per node in semantics

// Scratch (device globals; no allocations allowed).
__device__ int g_cnt[MAX_N];          // per-target edge counts (histogram)
__device__ int g_off[MAX_N + 1];      // CSR row offsets
__device__ int g_cursor[MAX_N];       // placement cursors (copy of offsets)
__device__ int g_srcs[MAX_EDGES];     // src indices sorted by tgt
__device__ int g_idx_is_64;           // 1 = int64 edge_index, 0 = int32

// ---------------------------------------------------------------------------
// Probe: decide whether edge_index is genuine int64 or packed int32 pairs.
// 32 lanes check 8 values each in parallel; any value outside [0,n) when read
// as int64 means the buffer actually holds int32 pairs.
// ---------------------------------------------------------------------------
__global__ void probe_dtype_kernel(const long long* __restrict__ ei64,
                                   long long n) {
    int lane = threadIdx.x;
    int bad = 0;
    #pragma unroll
    for (int i = 0; i < 8; i++) {
        long long v = ei64[lane * 8 + i];
        if (v < 0 || v >= n) bad = 1;
    }
    unsigned m = __ballot_sync(0xFFFFFFFFu, bad);
    if (lane == 0) g_idx_is_64 = (m == 0u) ? 1 : 0;
}

// ---------------------------------------------------------------------------
// Histogram of targets.
// ---------------------------------------------------------------------------
__global__ void hist_kernel(const void* __restrict__ ei_raw, int n_edges) {
    int e = blockIdx.x * blockDim.x + threadIdx.x;
    if (e >= n_edges) return;
    int tgt;
    if (g_idx_is_64) {
        tgt = (int)((const long long*)ei_raw)[2LL * e + 1];
    } else {
        tgt = ((const int*)ei_raw)[2LL * e + 1];
    }
    atomicAdd(&g_cnt[tgt], 1);
}

// ---------------------------------------------------------------------------
// Single-block exclusive scan over n counts -> g_off, g_cursor.
// 1024 threads, each owning a contiguous chunk; Hillis-Steele over partials.
// ---------------------------------------------------------------------------
#define SCAN_THREADS 1024
__global__ void scan_kernel(int n) {
    __shared__ int ssum[SCAN_THREADS];
    int t = threadIdx.x;
    int chunk = (n + SCAN_THREADS - 1) / SCAN_THREADS;
    int lo = t * chunk;
    int hi = min(lo + chunk, n);

    int sum = 0;
    for (int i = lo; i < hi; i++) sum += g_cnt[i];
    ssum[t] = sum;
    __syncthreads();

    for (int off = 1; off < SCAN_THREADS; off <<= 1) {
        int v = (t >= off) ? ssum[t - off] : 0;
        __syncthreads();
        ssum[t] += v;
        __syncthreads();
    }

    int run = (t == 0) ? 0 : ssum[t - 1];
    for (int i = lo; i < hi; i++) {
        int c = g_cnt[i];
        g_off[i] = run;
        g_cursor[i] = run;
        run += c;
    }
    if (t == SCAN_THREADS - 1) g_off[n] = run;
}

// ---------------------------------------------------------------------------
// Placement: bucket src indices by target (counting-sort scatter).
// ---------------------------------------------------------------------------
__global__ void place_kernel(const void* __restrict__ ei_raw, int n_edges) {
    int e = blockIdx.x * blockDim.x + threadIdx.x;
    if (e >= n_edges) return;
    int src, tgt;
    if (g_idx_is_64) {
        const long long* ei = (const long long*)ei_raw;
        src = (int)ei[2LL * e];
        tgt = (int)ei[2LL * e + 1];
    } else {
        const int* ei = (const int*)ei_raw;
        src = ei[2LL * e];
        tgt = ei[2LL * e + 1];
    }
    int pos = atomicAdd(&g_cursor[tgt], 1);
    g_srcs[pos] = src;
}

// ---------------------------------------------------------------------------
// Fused: CSR aggregation (register accumulators, one warp per node) ->
// mean -> smem -> 8x128 @ 128x128 GEMM -> exact GELU -> out.
// Block = 256 threads = 8 warps = 8 target nodes.
// ---------------------------------------------------------------------------
__global__ void agg_gemm_gelu_kernel(const float* __restrict__ sem,
                                     const float* __restrict__ W,
                                     float* __restrict__ out,
                                     int n) {
    __shared__ float s[8][HIDDEN];
    const int w    = threadIdx.x >> 5;
    const int lane = threadIdx.x & 31;
    const int node = blockIdx.x * 8 + w;

    float4 acc = make_float4(0.f, 0.f, 0.f, 0.f);
    float inv = 0.f;
    if (node < n) {
        const int beg = g_off[node];
        const int end = g_off[node + 1];
        int e = beg;
        // 2-edge unroll for MLP
        for (; e + 1 < end; e += 2) {
            int s0 = g_srcs[e];
            int s1 = g_srcs[e + 1];
            const float4 v0 = __ldg((const float4*)(sem + (size_t)s0 * SEQ_STRIDE) + lane);
            const float4 v1 = __ldg((const float4*)(sem + (size_t)s1 * SEQ_STRIDE) + lane);
            acc.x += v0.x + v1.x;
            acc.y += v0.y + v1.y;
            acc.z += v0.z + v1.z;
            acc.w += v0.w + v1.w;
        }
        if (e < end) {
            int s0 = g_srcs[e];
            const float4 v0 = __ldg((const float4*)(sem + (size_t)s0 * SEQ_STRIDE) + lane);
            acc.x += v0.x; acc.y += v0.y; acc.z += v0.z; acc.w += v0.w;
        }
        int cnt = end - beg;
        inv = 1.0f / (float)max(cnt, 1);
    }
    *(float4*)&s[w][lane * 4] =
        make_float4(acc.x * inv, acc.y * inv, acc.z * inv, acc.w * inv);
    __syncthreads();

    // GEMM: thread (rr, j) computes rows rr, rr+2, rr+4, rr+6 of column j.
    const int j  = threadIdx.x & 127;
    const int rr = threadIdx.x >> 7;   // 0 or 1
    float a0 = 0.f, a1 = 0.f, a2 = 0.f, a3 = 0.f;
    #pragma unroll 4
    for (int k = 0; k < HIDDEN; k++) {
        float wv = __ldg(W + k * HIDDEN + j);
        a0 = fmaf(s[rr    ][k], wv, a0);
        a1 = fmaf(s[rr + 2][k], wv, a1);
        a2 = fmaf(s[rr + 4][k], wv, a2);
        a3 = fmaf(s[rr + 6][k], wv, a3);
    }

    const int nb = blockIdx.x * 8;
    const float vals[4] = {a0, a1, a2, a3};
    #pragma unroll
    for (int i = 0; i < 4; i++) {
        int row = nb + rr + 2 * i;
        if (row < n) {
            float m = vals[i];
            // exact GELU: 0.5*x*(1 + erf(x/sqrt(2)))
            out[(size_t)row * HIDDEN + j] =
                0.5f * m * (1.0f + erff(m * 0.70710678118654752f));
        }
    }
}

// ---------------------------------------------------------------------------
// kernel_launch: probe -> memset counts -> hist -> scan -> place -> fused.
// All async on the default stream; graph-capturable; no allocations.
// Input order (metadata): semantics, attention_masks (unused), W, edge_index.
// ---------------------------------------------------------------------------
extern "C" void kernel_launch(void* const* d_in, const int* in_sizes, int n_in,
                              void* d_out, int out_size) {
    const float* sem = (const float*)d_in[0];
    const float* W   = (const float*)d_in[2];
    const void*  ei  = d_in[3];
    float* out = (float*)d_out;

    const int n       = in_sizes[0] / SEQ_STRIDE;   // 100000
    const int n_edges = in_sizes[3] / 2;            // 1600000

    void* cnt_ptr = nullptr;
    cudaGetSymbolAddress(&cnt_ptr, g_cnt);
    cudaMemsetAsync(cnt_ptr, 0, (size_t)n * sizeof(int));

    probe_dtype_kernel<<<1, 32>>>((const long long*)ei, (long long)n);

    int eb = (n_edges + 255) / 256;
    hist_kernel<<<eb, 256>>>(ei, n_edges);
    scan_kernel<<<1, SCAN_THREADS>>>(n);
    place_kernel<<<eb, 256>>>(ei, n_edges);

    int blocks = (n + 7) / 8;
    agg_gemm_gelu_kernel<<<blocks, 256>>>(sem, W, out, n);
}

// round 4
// speedup vs baseline: 1.0649x; 1.0649x over previous
#include <cuda_runtime.h>
#include <cuda_bf16.h>
#include <math.h>

// Problem constants (fixed by reference setup_inputs):
//   n = 100000 nodes, seq_len = 4, hidden = 128, n_edges = 1.6M
#define MAX_N      100000
#define MAX_EDGES  1600000
#define HIDDEN     128
#define SEQ_STRIDE (4 * 128)   // floats per node in semantics

// Scratch (device globals; no allocations allowed).
__device__ int g_cnt[MAX_N];          // per-target edge counts (histogram)
__device__ int g_off[MAX_N + 1];      // CSR row offsets
__device__ int g_cursor[MAX_N];       // placement cursors (copy of offsets)
__device__ int g_srcs[MAX_EDGES];     // src indices sorted by tgt
__device__ int g_idx_is_64;           // 1 = int64 edge_index, 0 = int32

// ---------------------------------------------------------------------------
// f32x2 packed-FMA helpers (Blackwell fma.rn.f32x2 — 2 FMA per issue slot).
// ---------------------------------------------------------------------------
__device__ __forceinline__ unsigned long long pack_f32x2(float lo, float hi) {
    unsigned long long r;
    asm("mov.b64 %0, {%1, %2};" : "=l"(r) : "f"(lo), "f"(hi));
    return r;
}
__device__ __forceinline__ void fma_f32x2(unsigned long long& d,
                                          unsigned long long a,
                                          unsigned long long b) {
    asm("fma.rn.f32x2 %0, %1, %2, %0;" : "+l"(d) : "l"(a), "l"(b));
}
__device__ __forceinline__ float hsum_f32x2(unsigned long long v) {
    float lo, hi;
    asm("mov.b64 {%0, %1}, %2;" : "=f"(lo), "=f"(hi) : "l"(v));
    return lo + hi;
}

// ---------------------------------------------------------------------------
// Probe: decide whether edge_index is genuine int64 or packed int32 pairs.
// ---------------------------------------------------------------------------
__global__ void probe_dtype_kernel(const long long* __restrict__ ei64,
                                   long long n) {
    int lane = threadIdx.x;
    int bad = 0;
    #pragma unroll
    for (int i = 0; i < 8; i++) {
        long long v = ei64[lane * 8 + i];
        if (v < 0 || v >= n) bad = 1;
    }
    unsigned m = __ballot_sync(0xFFFFFFFFu, bad);
    if (lane == 0) g_idx_is_64 = (m == 0u) ? 1 : 0;
}

// ---------------------------------------------------------------------------
// Histogram of targets.
// ---------------------------------------------------------------------------
__global__ void hist_kernel(const void* __restrict__ ei_raw, int n_edges) {
    int e = blockIdx.x * blockDim.x + threadIdx.x;
    if (e >= n_edges) return;
    int tgt;
    if (g_idx_is_64) {
        tgt = (int)((const long long*)ei_raw)[2LL * e + 1];
    } else {
        tgt = ((const int*)ei_raw)[2LL * e + 1];
    }
    atomicAdd(&g_cnt[tgt], 1);
}

// ---------------------------------------------------------------------------
// Single-block exclusive scan over n counts -> g_off, g_cursor.
// ---------------------------------------------------------------------------
#define SCAN_THREADS 1024
__global__ void scan_kernel(int n) {
    __shared__ int ssum[SCAN_THREADS];
    int t = threadIdx.x;
    int chunk = (n + SCAN_THREADS - 1) / SCAN_THREADS;
    int lo = t * chunk;
    int hi = min(lo + chunk, n);

    int sum = 0;
    for (int i = lo; i < hi; i++) sum += g_cnt[i];
    ssum[t] = sum;
    __syncthreads();

    for (int off = 1; off < SCAN_THREADS; off <<= 1) {
        int v = (t >= off) ? ssum[t - off] : 0;
        __syncthreads();
        ssum[t] += v;
        __syncthreads();
    }

    int run = (t == 0) ? 0 : ssum[t - 1];
    for (int i = lo; i < hi; i++) {
        int c = g_cnt[i];
        g_off[i] = run;
        g_cursor[i] = run;
        run += c;
    }
    if (t == SCAN_THREADS - 1) g_off[n] = run;
}

// ---------------------------------------------------------------------------
// Placement: bucket src indices by target (counting-sort scatter).
// ---------------------------------------------------------------------------
__global__ void place_kernel(const void* __restrict__ ei_raw, int n_edges) {
    int e = blockIdx.x * blockDim.x + threadIdx.x;
    if (e >= n_edges) return;
    int src, tgt;
    if (g_idx_is_64) {
        const long long* ei = (const long long*)ei_raw;
        src = (int)ei[2LL * e];
        tgt = (int)ei[2LL * e + 1];
    } else {
        const int* ei = (const int*)ei_raw;
        src = ei[2LL * e];
        tgt = ei[2LL * e + 1];
    }
    int pos = atomicAdd(&g_cursor[tgt], 1);
    g_srcs[pos] = src;
}

// ---------------------------------------------------------------------------
// Fused: CSR aggregation (register accumulators, warp per node, 2 nodes/warp)
// -> mean -> smem s[16][128] -> 16x128 @ 128x128 GEMM (f32x2 packed FMA,
// 8 rows per thread) -> exact GELU -> out.
// Block = 256 threads = 8 warps, 16 target nodes per block.
// ---------------------------------------------------------------------------
__global__ void __launch_bounds__(256, 4)
agg_gemm_gelu_kernel(const float* __restrict__ sem,
                     const float* __restrict__ W,
                     float* __restrict__ out,
                     int n) {
    __shared__ float s[16][HIDDEN];
    const int w    = threadIdx.x >> 5;
    const int lane = threadIdx.x & 31;
    const int base = blockIdx.x * 16;

    // ---- Gather phase: each warp aggregates 2 nodes ----
    #pragma unroll
    for (int half = 0; half < 2; half++) {
        const int r    = half * 8 + w;
        const int node = base + r;
        float4 acc = make_float4(0.f, 0.f, 0.f, 0.f);
        float inv = 0.f;
        if (node < n) {
            const int beg = g_off[node];
            const int end = g_off[node + 1];
            int e = beg;
            for (; e + 3 < end; e += 4) {
                int i0 = g_srcs[e],     i1 = g_srcs[e + 1];
                int i2 = g_srcs[e + 2], i3 = g_srcs[e + 3];
                float4 v0 = __ldg((const float4*)(sem + (size_t)i0 * SEQ_STRIDE) + lane);
                float4 v1 = __ldg((const float4*)(sem + (size_t)i1 * SEQ_STRIDE) + lane);
                float4 v2 = __ldg((const float4*)(sem + (size_t)i2 * SEQ_STRIDE) + lane);
                float4 v3 = __ldg((const float4*)(sem + (size_t)i3 * SEQ_STRIDE) + lane);
                acc.x += (v0.x + v1.x) + (v2.x + v3.x);
                acc.y += (v0.y + v1.y) + (v2.y + v3.y);
                acc.z += (v0.z + v1.z) + (v2.z + v3.z);
                acc.w += (v0.w + v1.w) + (v2.w + v3.w);
            }
            for (; e < end; e++) {
                int i0 = g_srcs[e];
                float4 v0 = __ldg((const float4*)(sem + (size_t)i0 * SEQ_STRIDE) + lane);
                acc.x += v0.x; acc.y += v0.y; acc.z += v0.z; acc.w += v0.w;
            }
            inv = 1.0f / (float)max(end - beg, 1);
        }
        *(float4*)&s[r][lane * 4] =
            make_float4(acc.x * inv, acc.y * inv, acc.z * inv, acc.w * inv);
    }
    __syncthreads();

    // ---- GEMM phase: thread (rr, j) computes rows rr, rr+2, ..., rr+14 ----
    const int j  = threadIdx.x & 127;
    const int rr = threadIdx.x >> 7;   // 0 or 1
    const float* Wj = W + j;

    unsigned long long acc2[8];
    #pragma unroll
    for (int i = 0; i < 8; i++) acc2[i] = 0ull;   // (0.f, 0.f)

    #pragma unroll 4
    for (int k = 0; k < HIDDEN; k += 2) {
        unsigned long long w2 =
            pack_f32x2(__ldg(Wj + k * HIDDEN), __ldg(Wj + (k + 1) * HIDDEN));
        #pragma unroll
        for (int i = 0; i < 8; i++) {
            // broadcast LDS.64 of (s[row][k], s[row][k+1])
            unsigned long long s2 =
                *(const unsigned long long*)&s[rr + 2 * i][k];
            fma_f32x2(acc2[i], s2, w2);
        }
    }

    #pragma unroll
    for (int i = 0; i < 8; i++) {
        int row = base + rr + 2 * i;
        if (row < n) {
            float m = hsum_f32x2(acc2[i]);
            // exact GELU: 0.5*x*(1 + erf(x/sqrt(2)))
            out[(size_t)row * HIDDEN + j] =
                0.5f * m * (1.0f + erff(m * 0.70710678118654752f));
        }
    }
}

// ---------------------------------------------------------------------------
// kernel_launch: probe -> memset counts -> hist -> scan -> place -> fused.
// All async on the default stream; graph-capturable; no allocations.
// Input order (metadata): semantics, attention_masks (unused), W, edge_index.
// ---------------------------------------------------------------------------
extern "C" void kernel_launch(void* const* d_in, const int* in_sizes, int n_in,
                              void* d_out, int out_size) {
    const float* sem = (const float*)d_in[0];
    const float* W   = (const float*)d_in[2];
    const void*  ei  = d_in[3];
    float* out = (float*)d_out;

    const int n       = in_sizes[0] / SEQ_STRIDE;   // 100000
    const int n_edges = in_sizes[3] / 2;            // 1600000

    void* cnt_ptr = nullptr;
    cudaGetSymbolAddress(&cnt_ptr, g_cnt);
    cudaMemsetAsync(cnt_ptr, 0, (size_t)n * sizeof(int));

    probe_dtype_kernel<<<1, 32>>>((const long long*)ei, (long long)n);

    int eb = (n_edges + 511) / 512;
    hist_kernel<<<eb, 512>>>(ei, n_edges);
    scan_kernel<<<1, SCAN_THREADS>>>(n);
    place_kernel<<<eb, 512>>>(ei, n_edges);

    int blocks = (n + 15) / 16;
    agg_gemm_gelu_kernel<<<blocks, 256>>>(sem, W, out, n);
}